// round 7
// baseline (speedup 1.0000x reference)
#include <cuda_runtime.h>
#include <cuda_fp16.h>

#define N_NODES 100000
#define N_EDGES 3200000
#define IN_F 128
#define HID 64
#define NC 16
#define NB ((N_NODES + 255) / 256)   // 391

// Scratch (static device globals — no allocation allowed)
__device__ __align__(16) float  g_dinv[N_NODES];
__device__ __align__(16) __half g_hs1h[N_NODES * HID];  // (x@W1)*dinv[row], fp16
__device__ __align__(16) float  g_hs2 [N_NODES * NC];   // (r1@W2)*dinv[row]
__device__ int g_cnt[N_NODES];        // in-degree (edges only)
__device__ int g_cur[N_NODES];        // fill cursor (seeded with offsets)
__device__ int g_off[N_NODES + 1];    // CSR offsets (by dst)
__device__ int g_bsum[NB];
__device__ int g_boff[NB];
__device__ int g_ecsr[N_EDGES];       // src ids grouped by dst
__device__ int g_is64;

// ---------------------------------------------------------------------------
// 0. detect int64 vs int32 edge_index (reads only first 4096 src entries)
__global__ void k_detect(const long long* __restrict__ ei) {
    __shared__ int bad;
    if (threadIdx.x == 0) bad = 0;
    __syncthreads();
    for (int i = threadIdx.x; i < 4096; i += 256) {
        long long s = ei[i];
        if (s < 0 || s >= (long long)N_NODES) atomicOr(&bad, 1);
    }
    __syncthreads();
    if (threadIdx.x == 0) g_is64 = bad ? 0 : 1;
}

// 1. zero degree counters
__global__ void k_zero() {
    int i = blockIdx.x * 256 + threadIdx.x;
    if (i < N_NODES) g_cnt[i] = 0;
}

// 2. degree count at dst (int atomics)
__global__ void k_deg(const void* __restrict__ ei) {
    int t = blockIdx.x * 256 + threadIdx.x;
    if (t >= N_EDGES) return;
    int dst;
    if (g_is64) dst = (int)((const long long*)ei)[N_EDGES + t];
    else        dst = ((const int*)ei)[N_EDGES + t];
    atomicAdd(&g_cnt[dst], 1);
}

// 3a. per-block sums
__global__ void k_scan1() {
    __shared__ int s[256];
    int t = threadIdx.x;
    int i = blockIdx.x * 256 + t;
    s[t] = (i < N_NODES) ? g_cnt[i] : 0;
    __syncthreads();
    #pragma unroll
    for (int o = 128; o > 0; o >>= 1) {
        if (t < o) s[t] += s[t + o];
        __syncthreads();
    }
    if (t == 0) g_bsum[blockIdx.x] = s[0];
}

// 3b. scan of block sums (single block, 512 threads, NB=391 <= 512)
__global__ void k_scan2() {
    __shared__ int s[512];
    int t = threadIdx.x;
    int mine = (t < NB) ? g_bsum[t] : 0;
    s[t] = mine;
    __syncthreads();
    #pragma unroll
    for (int o = 1; o < 512; o <<= 1) {
        int v = (t >= o) ? s[t - o] : 0;
        __syncthreads();
        s[t] += v;
        __syncthreads();
    }
    if (t < NB) g_boff[t] = s[t] - mine;   // exclusive
}

// 3c. within-block exclusive scan -> offsets; seed cursor; dinv = rsqrt(cnt+1)
__global__ void k_scan3() {
    __shared__ int s[256];
    int t = threadIdx.x;
    int i = blockIdx.x * 256 + t;
    int c = (i < N_NODES) ? g_cnt[i] : 0;
    s[t] = c;
    __syncthreads();
    #pragma unroll
    for (int o = 1; o < 256; o <<= 1) {
        int v = (t >= o) ? s[t - o] : 0;
        __syncthreads();
        s[t] += v;
        __syncthreads();
    }
    if (i < N_NODES) {
        int off = g_boff[blockIdx.x] + s[t] - c;
        g_off[i] = off;
        g_cur[i] = off;                    // absolute cursor for k_fill
        g_dinv[i] = rsqrtf((float)(c + 1));
    }
    if (i == 0) g_off[N_NODES] = N_EDGES;
}

// 4. CSR fill: bucket src by dst (cursor is absolute -> no g_off gather)
__global__ void k_fill(const void* __restrict__ ei) {
    int t = blockIdx.x * 256 + threadIdx.x;
    if (t >= N_EDGES) return;
    int src, dst;
    if (g_is64) {
        const long long* p = (const long long*)ei;
        src = (int)p[t]; dst = (int)p[N_EDGES + t];
    } else {
        const int* p = (const int*)ei;
        src = p[t]; dst = p[N_EDGES + t];
    }
    g_ecsr[atomicAdd(&g_cur[dst], 1)] = src;
}

// 5. GEMM1: hs1h[row][c] = half((x[row] . W1[:,c]) * dinv[row])
//    32 rows/block, blockDim(64,4), 8 rows per thread. W transposed+padded in smem.
__global__ __launch_bounds__(256) void k_gemm1(const float* __restrict__ x,
                                               const float* __restrict__ W1) {
    __shared__ float Ws[HID * 132];       // [col][k], pad 132 -> 33 KB
    __shared__ float xs[32 * IN_F];       // 16 KB
    const int tx = threadIdx.x;           // col 0..63
    const int ty = threadIdx.y;           // row group 0..3
    const int tid = tx + 64 * ty;
    const int base = blockIdx.x * 32;

    #pragma unroll
    for (int i = tid; i < IN_F * HID; i += 256) {
        int k = i >> 6, c = i & 63;
        Ws[c * 132 + k] = W1[i];
    }
    #pragma unroll
    for (int i = tid; i < 32 * IN_F; i += 256) {
        int r = i >> 7, k = i & 127;
        xs[i] = x[(size_t)(base + r) * IN_F + k];
    }
    __syncthreads();

    float acc[8] = {0.f, 0.f, 0.f, 0.f, 0.f, 0.f, 0.f, 0.f};
    #pragma unroll
    for (int k4 = 0; k4 < IN_F; k4 += 4) {
        float4 w = *(const float4*)&Ws[tx * 132 + k4];
        #pragma unroll
        for (int j = 0; j < 8; j++) {
            float4 xv = *(const float4*)&xs[(ty * 8 + j) * IN_F + k4];
            acc[j] += xv.x * w.x + xv.y * w.y + xv.z * w.z + xv.w * w.w;
        }
    }
    #pragma unroll
    for (int j = 0; j < 8; j++) {
        int row = base + ty * 8 + j;
        g_hs1h[(size_t)row * HID + tx] = __float2half(acc[j] * g_dinv[row]);
    }
}

// unpack 8 halves (uint4) and accumulate into fp32
__device__ __forceinline__ void add8(float a[8], uint4 v) {
    float2 f0 = __half22float2(*reinterpret_cast<__half2*>(&v.x));
    float2 f1 = __half22float2(*reinterpret_cast<__half2*>(&v.y));
    float2 f2 = __half22float2(*reinterpret_cast<__half2*>(&v.z));
    float2 f3 = __half22float2(*reinterpret_cast<__half2*>(&v.w));
    a[0] += f0.x; a[1] += f0.y; a[2] += f1.x; a[3] += f1.y;
    a[4] += f2.x; a[5] += f2.y; a[6] += f3.x; a[7] += f3.y;
}

// 6. Layer-1 aggregation (CSR gather, fp16 rows) fused with relu+bias+GEMM2.
//    8-thread groups, 32 nodes/block. Each lane owns features [lane*8, lane*8+8).
__global__ __launch_bounds__(256) void k_agg1(const float* __restrict__ b1,
                                              const float* __restrict__ W2) {
    __shared__ float W2s[HID * NC];       // 4 KB
    __shared__ float r1s[32][65];         // padded, 8.1 KB
    const int t = threadIdx.x;
    const int g = t >> 3;
    const int lane = t & 7;
    #pragma unroll
    for (int i = t; i < HID * NC; i += 256) W2s[i] = W2[i];

    const int n = blockIdx.x * 32 + g;    // grid = 3125, exact
    const int start = g_off[n], end = g_off[n + 1];
    const uint4* hv = (const uint4*)g_hs1h;   // 8 uint4 per row

    float a[8] = {0.f, 0.f, 0.f, 0.f, 0.f, 0.f, 0.f, 0.f};
    add8(a, hv[(size_t)n * 8 + lane]);        // self loop
    const unsigned m = 0xFFu << ((t & 31) & 24);

    int j = start;
    for (; j + 8 <= end; j += 8) {
        int sv = g_ecsr[j + lane];
        #pragma unroll
        for (int q = 0; q < 8; q++) {
            int s = __shfl_sync(m, sv, q, 8);
            add8(a, hv[(size_t)s * 8 + lane]);
        }
    }
    int rem = end - j;
    if (rem > 0) {
        int sv = (lane < rem) ? g_ecsr[j + lane] : 0;
        for (int q = 0; q < rem; q++) {
            int s = __shfl_sync(m, sv, q, 8);
            add8(a, hv[(size_t)s * 8 + lane]);
        }
    }

    const float d = g_dinv[n];
    #pragma unroll
    for (int i = 0; i < 8; i++)
        r1s[g][lane * 8 + i] = fmaxf(a[i] * d + b1[lane * 8 + i], 0.f);
    __syncthreads();

    // GEMM2: each thread computes 2 output cols (lane, lane+8) for node n
    float o0 = 0.f, o1 = 0.f;
    #pragma unroll
    for (int k = 0; k < HID; k++) {
        float r = r1s[g][k];
        o0 += r * W2s[k * NC + lane];
        o1 += r * W2s[k * NC + lane + 8];
    }
    g_hs2[(size_t)n * NC + lane]     = o0 * d;
    g_hs2[(size_t)n * NC + lane + 8] = o1 * d;
}

// 7. Layer-2 aggregation fused with final bias; writes d_out.
//    4-thread groups, 64 nodes/block
__global__ __launch_bounds__(256) void k_agg2(const float* __restrict__ b2,
                                              float* __restrict__ out) {
    const int t = threadIdx.x;
    const int g = t >> 2;
    const int lane = t & 3;
    const int n = blockIdx.x * 64 + g;
    if (n >= N_NODES) return;

    const int start = g_off[n], end = g_off[n + 1];
    float4 acc = ((const float4*)g_hs2)[(size_t)n * 4 + lane];   // self loop
    const int li = t & 31;
    const unsigned qm = 0xFu << (li & 28);

    int j = start;
    for (; j + 4 <= end; j += 4) {
        int sv = g_ecsr[j + lane];
        #pragma unroll
        for (int q = 0; q < 4; q++) {
            int s = __shfl_sync(qm, sv, q, 4);
            float4 v = ((const float4*)g_hs2)[(size_t)s * 4 + lane];
            acc.x += v.x; acc.y += v.y; acc.z += v.z; acc.w += v.w;
        }
    }
    int rem = end - j;
    if (rem > 0) {
        int sv = (lane < rem) ? g_ecsr[j + lane] : 0;
        for (int q = 0; q < rem; q++) {
            int s = __shfl_sync(qm, sv, q, 4);
            float4 v = ((const float4*)g_hs2)[(size_t)s * 4 + lane];
            acc.x += v.x; acc.y += v.y; acc.z += v.z; acc.w += v.w;
        }
    }

    const float d = g_dinv[n];
    float4 bb = ((const float4*)b2)[lane];
    float4 r;
    r.x = acc.x * d + bb.x;
    r.y = acc.y * d + bb.y;
    r.z = acc.z * d + bb.z;
    r.w = acc.w * d + bb.w;
    ((float4*)out)[(size_t)n * 4 + lane] = r;
}

extern "C" void kernel_launch(void* const* d_in, const int* in_sizes, int n_in,
                              void* d_out, int out_size) {
    const float* x  = (const float*)d_in[0];
    const void*  ei = d_in[1];
    const float* W1 = (const float*)d_in[2];
    const float* b1 = (const float*)d_in[3];
    const float* W2 = (const float*)d_in[4];
    const float* b2 = (const float*)d_in[5];
    float* out = (float*)d_out;

    k_detect<<<1, 256>>>((const long long*)ei);
    k_zero  <<<NB, 256>>>();
    k_deg   <<<(N_EDGES + 255) / 256, 256>>>(ei);
    k_scan1 <<<NB, 256>>>();
    k_scan2 <<<1, 512>>>();
    k_scan3 <<<NB, 256>>>();
    k_fill  <<<(N_EDGES + 255) / 256, 256>>>(ei);
    k_gemm1 <<<N_NODES / 32, dim3(64, 4)>>>(x, W1);
    k_agg1  <<<N_NODES / 32, 256>>>(b1, W2);
    k_agg2  <<<(N_NODES + 63) / 64, 256>>>(b2, out);
}

// round 9
// speedup vs baseline: 1.3205x; 1.3205x over previous
#include <cuda_runtime.h>
#include <cuda_fp16.h>

#define N_NODES 100000
#define N_EDGES 3200000
#define IN_F 128
#define HID 64
#define NC 16
#define NB ((N_NODES + 255) / 256)   // 391

// Scratch (static device globals — no allocation allowed)
__device__ __align__(16) float  g_dinv[N_NODES];
__device__ __align__(16) __half g_hs1h[N_NODES * HID];  // (x@W1)*dinv[row], fp16
__device__ __align__(16) float  g_hs2 [N_NODES * NC];   // (r1@W2)*dinv[row]
__device__ int g_cnt[N_NODES];        // in-degree (edges only)
__device__ int g_cur[N_NODES];        // fill cursor (seeded with offsets)
__device__ int g_off[N_NODES + 1];    // CSR offsets (by dst)
__device__ int g_bsum[NB];
__device__ int g_boff[NB];
__device__ int g_ecsr[N_EDGES];       // src ids grouped by dst
__device__ int g_is64;

// ---------------------------------------------------------------------------
// 0. detect int64 vs int32 edge_index (reads only first 4096 src entries)
__global__ void k_detect(const long long* __restrict__ ei) {
    __shared__ int bad;
    if (threadIdx.x == 0) bad = 0;
    __syncthreads();
    for (int i = threadIdx.x; i < 4096; i += 256) {
        long long s = ei[i];
        if (s < 0 || s >= (long long)N_NODES) atomicOr(&bad, 1);
    }
    __syncthreads();
    if (threadIdx.x == 0) g_is64 = bad ? 0 : 1;
}

// 1. zero degree counters
__global__ void k_zero() {
    int i = blockIdx.x * 256 + threadIdx.x;
    if (i < N_NODES) g_cnt[i] = 0;
}

// 2. degree count at dst (int atomics)
__global__ void k_deg(const void* __restrict__ ei) {
    int t = blockIdx.x * 256 + threadIdx.x;
    if (t >= N_EDGES) return;
    int dst;
    if (g_is64) dst = (int)((const long long*)ei)[N_EDGES + t];
    else        dst = ((const int*)ei)[N_EDGES + t];
    atomicAdd(&g_cnt[dst], 1);
}

// 3a. per-block sums
__global__ void k_scan1() {
    __shared__ int s[256];
    int t = threadIdx.x;
    int i = blockIdx.x * 256 + t;
    s[t] = (i < N_NODES) ? g_cnt[i] : 0;
    __syncthreads();
    #pragma unroll
    for (int o = 128; o > 0; o >>= 1) {
        if (t < o) s[t] += s[t + o];
        __syncthreads();
    }
    if (t == 0) g_bsum[blockIdx.x] = s[0];
}

// 3b. scan of block sums (single block, 512 threads, NB=391 <= 512)
__global__ void k_scan2() {
    __shared__ int s[512];
    int t = threadIdx.x;
    int mine = (t < NB) ? g_bsum[t] : 0;
    s[t] = mine;
    __syncthreads();
    #pragma unroll
    for (int o = 1; o < 512; o <<= 1) {
        int v = (t >= o) ? s[t - o] : 0;
        __syncthreads();
        s[t] += v;
        __syncthreads();
    }
    if (t < NB) g_boff[t] = s[t] - mine;   // exclusive
}

// 3c. within-block exclusive scan -> offsets; seed cursor; dinv = rsqrt(cnt+1)
__global__ void k_scan3() {
    __shared__ int s[256];
    int t = threadIdx.x;
    int i = blockIdx.x * 256 + t;
    int c = (i < N_NODES) ? g_cnt[i] : 0;
    s[t] = c;
    __syncthreads();
    #pragma unroll
    for (int o = 1; o < 256; o <<= 1) {
        int v = (t >= o) ? s[t - o] : 0;
        __syncthreads();
        s[t] += v;
        __syncthreads();
    }
    if (i < N_NODES) {
        int off = g_boff[blockIdx.x] + s[t] - c;
        g_off[i] = off;
        g_cur[i] = off;                    // absolute cursor for k_fill
        g_dinv[i] = rsqrtf((float)(c + 1));
    }
    if (i == 0) g_off[N_NODES] = N_EDGES;
}

// 4. CSR fill: bucket src by dst (cursor is absolute -> no g_off gather)
__global__ void k_fill(const void* __restrict__ ei) {
    int t = blockIdx.x * 256 + threadIdx.x;
    if (t >= N_EDGES) return;
    int src, dst;
    if (g_is64) {
        const long long* p = (const long long*)ei;
        src = (int)p[t]; dst = (int)p[N_EDGES + t];
    } else {
        const int* p = (const int*)ei;
        src = p[t]; dst = p[N_EDGES + t];
    }
    g_ecsr[atomicAdd(&g_cur[dst], 1)] = src;
}

// 5. GEMM1 (R6-proven geometry): hs1h[row][c] = half((x[row].W1[:,c]) * dinv[row])
//    block: 16 rows x 64 cols, blockDim(64,4), each thread 4 rows x 1 col
__global__ __launch_bounds__(256) void k_gemm1(const float* __restrict__ x,
                                               const float* __restrict__ W1) {
    __shared__ float Ws[IN_F * HID];      // 32 KB
    __shared__ float xs[16 * IN_F];       // 8 KB
    const int tx = threadIdx.x;           // col 0..63
    const int ty = threadIdx.y;           // row group 0..3
    const int tid = tx + 64 * ty;
    const int base = blockIdx.x * 16;

    #pragma unroll
    for (int i = tid; i < IN_F * HID; i += 256) Ws[i] = W1[i];
    #pragma unroll
    for (int i = tid; i < 16 * IN_F; i += 256) {
        int r = i >> 7, k = i & 127;
        xs[i] = x[(size_t)(base + r) * IN_F + k];
    }
    __syncthreads();

    float acc0 = 0.f, acc1 = 0.f, acc2 = 0.f, acc3 = 0.f;
    #pragma unroll
    for (int k4 = 0; k4 < IN_F; k4 += 4) {
        float4 x0 = *(const float4*)&xs[(ty * 4 + 0) * IN_F + k4];
        float4 x1 = *(const float4*)&xs[(ty * 4 + 1) * IN_F + k4];
        float4 x2 = *(const float4*)&xs[(ty * 4 + 2) * IN_F + k4];
        float4 x3 = *(const float4*)&xs[(ty * 4 + 3) * IN_F + k4];
        float w0 = Ws[(k4 + 0) * HID + tx];
        float w1 = Ws[(k4 + 1) * HID + tx];
        float w2 = Ws[(k4 + 2) * HID + tx];
        float w3 = Ws[(k4 + 3) * HID + tx];
        acc0 += x0.x * w0 + x0.y * w1 + x0.z * w2 + x0.w * w3;
        acc1 += x1.x * w0 + x1.y * w1 + x1.z * w2 + x1.w * w3;
        acc2 += x2.x * w0 + x2.y * w1 + x2.z * w2 + x2.w * w3;
        acc3 += x3.x * w0 + x3.y * w1 + x3.z * w2 + x3.w * w3;
    }
    float a[4] = {acc0, acc1, acc2, acc3};
    #pragma unroll
    for (int j = 0; j < 4; j++) {
        int row = base + ty * 4 + j;
        g_hs1h[(size_t)row * HID + tx] = __float2half(a[j] * g_dinv[row]);
    }
}

// 6. Layer-1 aggregation (CSR gather, fp16 rows) fused with relu+bias+GEMM2.
//    R6 geometry: 16-thread groups, 16 nodes/block; lane owns features
//    [lane*4, lane*4+4) as one uint2 (4 halves, 8 B).
__global__ __launch_bounds__(256) void k_agg1(const float* __restrict__ b1,
                                              const float* __restrict__ W2) {
    __shared__ float W2s[HID * NC];       // 4 KB
    __shared__ float r1s[16][65];         // padded
    const int t = threadIdx.x;
    const int g = t >> 4;
    const int lane = t & 15;
    #pragma unroll
    for (int i = t; i < HID * NC; i += 256) W2s[i] = W2[i];

    const int n = blockIdx.x * 16 + g;    // grid = 6250, exact
    const int start = g_off[n], end = g_off[n + 1];
    const uint2* hv = (const uint2*)g_hs1h;   // 16 uint2 per row

    float4 acc = make_float4(0.f, 0.f, 0.f, 0.f);
    {
        uint2 v = hv[(size_t)n * 16 + lane];  // self loop
        float2 f0 = __half22float2(*reinterpret_cast<__half2*>(&v.x));
        float2 f1 = __half22float2(*reinterpret_cast<__half2*>(&v.y));
        acc.x += f0.x; acc.y += f0.y; acc.z += f1.x; acc.w += f1.y;
    }
    const unsigned hm = 0xFFFFu << (t & 16);

    int j = start;
    for (; j + 16 <= end; j += 16) {
        int sv = g_ecsr[j + lane];
        #pragma unroll
        for (int q = 0; q < 16; q++) {
            int s = __shfl_sync(hm, sv, q, 16);
            uint2 v = hv[(size_t)s * 16 + lane];
            float2 f0 = __half22float2(*reinterpret_cast<__half2*>(&v.x));
            float2 f1 = __half22float2(*reinterpret_cast<__half2*>(&v.y));
            acc.x += f0.x; acc.y += f0.y; acc.z += f1.x; acc.w += f1.y;
        }
    }
    int rem = end - j;
    if (rem > 0) {
        int sv = (lane < rem) ? g_ecsr[j + lane] : 0;
        for (int q = 0; q < rem; q++) {
            int s = __shfl_sync(hm, sv, q, 16);
            uint2 v = hv[(size_t)s * 16 + lane];
            float2 f0 = __half22float2(*reinterpret_cast<__half2*>(&v.x));
            float2 f1 = __half22float2(*reinterpret_cast<__half2*>(&v.y));
            acc.x += f0.x; acc.y += f0.y; acc.z += f1.x; acc.w += f1.y;
        }
    }

    const float d = g_dinv[n];
    float4 bb = ((const float4*)b1)[lane];
    r1s[g][lane * 4 + 0] = fmaxf(acc.x * d + bb.x, 0.f);
    r1s[g][lane * 4 + 1] = fmaxf(acc.y * d + bb.y, 0.f);
    r1s[g][lane * 4 + 2] = fmaxf(acc.z * d + bb.z, 0.f);
    r1s[g][lane * 4 + 3] = fmaxf(acc.w * d + bb.w, 0.f);
    __syncthreads();

    float o = 0.f;
    #pragma unroll
    for (int k = 0; k < HID; k++)
        o += r1s[g][k] * W2s[k * NC + lane];
    g_hs2[(size_t)n * NC + lane] = o * d;
}

// 7. Layer-2 aggregation fused with final bias; writes d_out.
//    4-thread groups, 64 nodes/block
__global__ __launch_bounds__(256) void k_agg2(const float* __restrict__ b2,
                                              float* __restrict__ out) {
    const int t = threadIdx.x;
    const int g = t >> 2;
    const int lane = t & 3;
    const int n = blockIdx.x * 64 + g;
    if (n >= N_NODES) return;

    const int start = g_off[n], end = g_off[n + 1];
    float4 acc = ((const float4*)g_hs2)[(size_t)n * 4 + lane];   // self loop
    const int li = t & 31;
    const unsigned qm = 0xFu << (li & 28);

    int j = start;
    for (; j + 4 <= end; j += 4) {
        int sv = g_ecsr[j + lane];
        #pragma unroll
        for (int q = 0; q < 4; q++) {
            int s = __shfl_sync(qm, sv, q, 4);
            float4 v = ((const float4*)g_hs2)[(size_t)s * 4 + lane];
            acc.x += v.x; acc.y += v.y; acc.z += v.z; acc.w += v.w;
        }
    }
    int rem = end - j;
    if (rem > 0) {
        int sv = (lane < rem) ? g_ecsr[j + lane] : 0;
        for (int q = 0; q < rem; q++) {
            int s = __shfl_sync(qm, sv, q, 4);
            float4 v = ((const float4*)g_hs2)[(size_t)s * 4 + lane];
            acc.x += v.x; acc.y += v.y; acc.z += v.z; acc.w += v.w;
        }
    }

    const float d = g_dinv[n];
    float4 bb = ((const float4*)b2)[lane];
    float4 r;
    r.x = acc.x * d + bb.x;
    r.y = acc.y * d + bb.y;
    r.z = acc.z * d + bb.z;
    r.w = acc.w * d + bb.w;
    ((float4*)out)[(size_t)n * 4 + lane] = r;
}

extern "C" void kernel_launch(void* const* d_in, const int* in_sizes, int n_in,
                              void* d_out, int out_size) {
    const float* x  = (const float*)d_in[0];
    const void*  ei = d_in[1];
    const float* W1 = (const float*)d_in[2];
    const float* b1 = (const float*)d_in[3];
    const float* W2 = (const float*)d_in[4];
    const float* b2 = (const float*)d_in[5];
    float* out = (float*)d_out;

    k_detect<<<1, 256>>>((const long long*)ei);
    k_zero  <<<NB, 256>>>();
    k_deg   <<<(N_EDGES + 255) / 256, 256>>>(ei);
    k_scan1 <<<NB, 256>>>();
    k_scan2 <<<1, 512>>>();
    k_scan3 <<<NB, 256>>>();
    k_fill  <<<(N_EDGES + 255) / 256, 256>>>(ei);
    k_gemm1 <<<N_NODES / 16, dim3(64, 4)>>>(x, W1);
    k_agg1  <<<N_NODES / 16, 256>>>(b1, W2);
    k_agg2  <<<(N_NODES + 63) / 64, 256>>>(b2, out);
}

// round 11
// speedup vs baseline: 1.5208x; 1.1517x over previous
#include <cuda_runtime.h>
#include <cuda_fp16.h>

#define N_NODES 100000
#define N_EDGES 3200000
#define IN_F 128
#define HID 64
#define NC 16
#define NB ((N_NODES + 255) / 256)      // 391
#define FILL_BLKS (N_EDGES / 256)       // 12500 exact
#define GEMM_BLKS (N_NODES / 16)        // 6250 exact

// Scratch (static device globals — no allocation allowed)
__device__ __align__(16) float  g_dinv[N_NODES];
__device__ __align__(16) __half g_hs1h[N_NODES * HID];  // (x@W1)*dinv[row], fp16
__device__ __align__(16) float  g_hs2 [N_NODES * NC];   // (r1@W2)*dinv[row]
__device__ int g_cnt[N_NODES];        // in-degree (edges only)
__device__ int g_cur[N_NODES];        // fill cursor (seeded with offsets)
__device__ int g_off[N_NODES + 1];    // CSR offsets (by dst)
__device__ int g_bsum[NB];
__device__ int g_ecsr[N_EDGES];       // src ids grouped by dst
__device__ int g_is64;

// ---------------------------------------------------------------------------
// 0. fused: zero degree counters + detect int64 vs int32 (block 0)
__global__ void k_prep(const long long* __restrict__ ei) {
    int i = blockIdx.x * 256 + threadIdx.x;
    if (i < N_NODES) g_cnt[i] = 0;
    if (blockIdx.x == 0) {
        __shared__ int bad;
        if (threadIdx.x == 0) bad = 0;
        __syncthreads();
        for (int k = threadIdx.x; k < 4096; k += 256) {
            long long s = ei[k];
            if (s < 0 || s >= (long long)N_NODES) atomicOr(&bad, 1);
        }
        __syncthreads();
        if (threadIdx.x == 0) g_is64 = bad ? 0 : 1;
    }
}

// 1. degree count at dst (int atomics)
__global__ void k_deg(const void* __restrict__ ei) {
    int t = blockIdx.x * 256 + threadIdx.x;
    if (t >= N_EDGES) return;
    int dst;
    if (g_is64) dst = (int)((const long long*)ei)[N_EDGES + t];
    else        dst = ((const int*)ei)[N_EDGES + t];
    atomicAdd(&g_cnt[dst], 1);
}

// 2. per-block sums
__global__ void k_scan1() {
    __shared__ int s[256];
    int t = threadIdx.x;
    int i = blockIdx.x * 256 + t;
    s[t] = (i < N_NODES) ? g_cnt[i] : 0;
    __syncthreads();
    #pragma unroll
    for (int o = 128; o > 0; o >>= 1) {
        if (t < o) s[t] += s[t + o];
        __syncthreads();
    }
    if (t == 0) g_bsum[blockIdx.x] = s[0];
}

// 3. offsets: each block sums bsums below it (391 values — cheap), then
//    intra-block exclusive scan; seed cursor; dinv = rsqrt(cnt+1)
__global__ void k_scan3() {
    __shared__ int s[256];
    __shared__ int blockpre;
    int t = threadIdx.x;

    // sum of g_bsum[0 .. blockIdx-1]
    int partial = 0;
    for (int i = t; i < blockIdx.x; i += 256) partial += g_bsum[i];
    s[t] = partial;
    __syncthreads();
    #pragma unroll
    for (int o = 128; o > 0; o >>= 1) {
        if (t < o) s[t] += s[t + o];
        __syncthreads();
    }
    if (t == 0) blockpre = s[0];
    __syncthreads();
    int boff = blockpre;
    __syncthreads();                       // protect s[] reuse

    int i = blockIdx.x * 256 + t;
    int c = (i < N_NODES) ? g_cnt[i] : 0;
    s[t] = c;
    __syncthreads();
    #pragma unroll
    for (int o = 1; o < 256; o <<= 1) {
        int v = (t >= o) ? s[t - o] : 0;
        __syncthreads();
        s[t] += v;
        __syncthreads();
    }
    if (i < N_NODES) {
        int off = boff + s[t] - c;
        g_off[i] = off;
        g_cur[i] = off;                    // absolute cursor for fill
        g_dinv[i] = rsqrtf((float)(c + 1));
    }
    if (i == 0) g_off[N_NODES] = N_EDGES;
}

// 4. fused CSR-fill + GEMM1 (both depend only on scan3 outputs).
//    blocks [0, FILL_BLKS): fill;  [FILL_BLKS, +GEMM_BLKS): gemm1.
__global__ __launch_bounds__(256) void k_fill_gemm1(const void* __restrict__ ei,
                                                    const float* __restrict__ x,
                                                    const float* __restrict__ W1) {
    __shared__ float Ws[IN_F * HID];      // 32 KB (gemm branch only)
    __shared__ float xs[16 * IN_F];       // 8 KB
    if (blockIdx.x < FILL_BLKS) {
        int t = blockIdx.x * 256 + threadIdx.x;   // exact, no guard
        int src, dst;
        if (g_is64) {
            const long long* p = (const long long*)ei;
            src = (int)p[t]; dst = (int)p[N_EDGES + t];
        } else {
            const int* p = (const int*)ei;
            src = p[t]; dst = p[N_EDGES + t];
        }
        g_ecsr[atomicAdd(&g_cur[dst], 1)] = src;
        return;
    }

    const int tid = threadIdx.x;
    const int tx = tid & 63;              // col 0..63
    const int ty = tid >> 6;              // row group 0..3
    const int base = (blockIdx.x - FILL_BLKS) * 16;

    #pragma unroll
    for (int i = tid; i < IN_F * HID; i += 256) Ws[i] = W1[i];
    #pragma unroll
    for (int i = tid; i < 16 * IN_F; i += 256) {
        int r = i >> 7, k = i & 127;
        xs[i] = x[(size_t)(base + r) * IN_F + k];
    }
    __syncthreads();

    float acc0 = 0.f, acc1 = 0.f, acc2 = 0.f, acc3 = 0.f;
    #pragma unroll
    for (int k4 = 0; k4 < IN_F; k4 += 4) {
        float4 x0 = *(const float4*)&xs[(ty * 4 + 0) * IN_F + k4];
        float4 x1 = *(const float4*)&xs[(ty * 4 + 1) * IN_F + k4];
        float4 x2 = *(const float4*)&xs[(ty * 4 + 2) * IN_F + k4];
        float4 x3 = *(const float4*)&xs[(ty * 4 + 3) * IN_F + k4];
        float w0 = Ws[(k4 + 0) * HID + tx];
        float w1 = Ws[(k4 + 1) * HID + tx];
        float w2 = Ws[(k4 + 2) * HID + tx];
        float w3 = Ws[(k4 + 3) * HID + tx];
        acc0 += x0.x * w0 + x0.y * w1 + x0.z * w2 + x0.w * w3;
        acc1 += x1.x * w0 + x1.y * w1 + x1.z * w2 + x1.w * w3;
        acc2 += x2.x * w0 + x2.y * w1 + x2.z * w2 + x2.w * w3;
        acc3 += x3.x * w0 + x3.y * w1 + x3.z * w2 + x3.w * w3;
    }
    float a[4] = {acc0, acc1, acc2, acc3};
    #pragma unroll
    for (int j = 0; j < 4; j++) {
        int row = base + ty * 4 + j;
        g_hs1h[(size_t)row * HID + tx] = __float2half(a[j] * g_dinv[row]);
    }
}

// 5. Layer-1 aggregation (CSR gather, fp16 rows, HADD2 inner loop) fused with
//    relu+bias+GEMM2. 16-thread groups, 16 nodes/block; lane owns 4 features
//    as one uint2 (2 half2). fp16 partials flushed to fp32 every 8 edges.
__global__ __launch_bounds__(256) void k_agg1(const float* __restrict__ b1,
                                              const float* __restrict__ W2) {
    __shared__ float W2s[HID * NC];       // 4 KB
    __shared__ float r1s[16][65];         // padded
    const int t = threadIdx.x;
    const int g = t >> 4;
    const int lane = t & 15;
    #pragma unroll
    for (int i = t; i < HID * NC; i += 256) W2s[i] = W2[i];

    const int n = blockIdx.x * 16 + g;    // grid = 6250, exact
    const int start = g_off[n], end = g_off[n + 1];
    const uint2* hv = (const uint2*)g_hs1h;   // 16 uint2 per row

    float4 acc = make_float4(0.f, 0.f, 0.f, 0.f);
    {
        uint2 v = hv[(size_t)n * 16 + lane];  // self loop (fp32 unpack)
        float2 f0 = __half22float2(*reinterpret_cast<__half2*>(&v.x));
        float2 f1 = __half22float2(*reinterpret_cast<__half2*>(&v.y));
        acc.x += f0.x; acc.y += f0.y; acc.z += f1.x; acc.w += f1.y;
    }
    const unsigned hm = 0xFFFFu << (t & 16);

    int j = start;
    for (; j + 16 <= end; j += 16) {
        int sv = g_ecsr[j + lane];
        #pragma unroll
        for (int h = 0; h < 2; h++) {     // two 8-edge sub-batches
            __half2 p0 = __half2half2(__ushort_as_half(0));
            __half2 p1 = p0;
            #pragma unroll
            for (int q = 0; q < 8; q++) {
                int s = __shfl_sync(hm, sv, h * 8 + q, 16);
                uint2 v = hv[(size_t)s * 16 + lane];
                p0 = __hadd2(p0, *reinterpret_cast<__half2*>(&v.x));
                p1 = __hadd2(p1, *reinterpret_cast<__half2*>(&v.y));
            }
            float2 f0 = __half22float2(p0);
            float2 f1 = __half22float2(p1);
            acc.x += f0.x; acc.y += f0.y; acc.z += f1.x; acc.w += f1.y;
        }
    }
    int rem = end - j;
    if (rem > 0) {                        // <=15 edges, fp32 unpack path
        int sv = (lane < rem) ? g_ecsr[j + lane] : 0;
        for (int q = 0; q < rem; q++) {
            int s = __shfl_sync(hm, sv, q, 16);
            uint2 v = hv[(size_t)s * 16 + lane];
            float2 f0 = __half22float2(*reinterpret_cast<__half2*>(&v.x));
            float2 f1 = __half22float2(*reinterpret_cast<__half2*>(&v.y));
            acc.x += f0.x; acc.y += f0.y; acc.z += f1.x; acc.w += f1.y;
        }
    }

    const float d = g_dinv[n];
    float4 bb = ((const float4*)b1)[lane];
    r1s[g][lane * 4 + 0] = fmaxf(acc.x * d + bb.x, 0.f);
    r1s[g][lane * 4 + 1] = fmaxf(acc.y * d + bb.y, 0.f);
    r1s[g][lane * 4 + 2] = fmaxf(acc.z * d + bb.z, 0.f);
    r1s[g][lane * 4 + 3] = fmaxf(acc.w * d + bb.w, 0.f);
    __syncthreads();

    float o = 0.f;
    #pragma unroll
    for (int k = 0; k < HID; k++)
        o += r1s[g][k] * W2s[k * NC + lane];
    g_hs2[(size_t)n * NC + lane] = o * d;
}

// 6. Layer-2 aggregation fused with final bias; writes d_out.
//    4-thread groups, 64 nodes/block
__global__ __launch_bounds__(256) void k_agg2(const float* __restrict__ b2,
                                              float* __restrict__ out) {
    const int t = threadIdx.x;
    const int g = t >> 2;
    const int lane = t & 3;
    const int n = blockIdx.x * 64 + g;
    if (n >= N_NODES) return;

    const int start = g_off[n], end = g_off[n + 1];
    float4 acc = ((const float4*)g_hs2)[(size_t)n * 4 + lane];   // self loop
    const int li = t & 31;
    const unsigned qm = 0xFu << (li & 28);

    int j = start;
    for (; j + 4 <= end; j += 4) {
        int sv = g_ecsr[j + lane];
        #pragma unroll
        for (int q = 0; q < 4; q++) {
            int s = __shfl_sync(qm, sv, q, 4);
            float4 v = ((const float4*)g_hs2)[(size_t)s * 4 + lane];
            acc.x += v.x; acc.y += v.y; acc.z += v.z; acc.w += v.w;
        }
    }
    int rem = end - j;
    if (rem > 0) {
        int sv = (lane < rem) ? g_ecsr[j + lane] : 0;
        for (int q = 0; q < rem; q++) {
            int s = __shfl_sync(qm, sv, q, 4);
            float4 v = ((const float4*)g_hs2)[(size_t)s * 4 + lane];
            acc.x += v.x; acc.y += v.y; acc.z += v.z; acc.w += v.w;
        }
    }

    const float d = g_dinv[n];
    float4 bb = ((const float4*)b2)[lane];
    float4 r;
    r.x = acc.x * d + bb.x;
    r.y = acc.y * d + bb.y;
    r.z = acc.z * d + bb.z;
    r.w = acc.w * d + bb.w;
    ((float4*)out)[(size_t)n * 4 + lane] = r;
}

extern "C" void kernel_launch(void* const* d_in, const int* in_sizes, int n_in,
                              void* d_out, int out_size) {
    const float* x  = (const float*)d_in[0];
    const void*  ei = d_in[1];
    const float* W1 = (const float*)d_in[2];
    const float* b1 = (const float*)d_in[3];
    const float* W2 = (const float*)d_in[4];
    const float* b2 = (const float*)d_in[5];
    float* out = (float*)d_out;

    k_prep      <<<NB, 256>>>((const long long*)ei);          // launch 0
    k_deg       <<<(N_EDGES + 255) / 256, 256>>>(ei);         // launch 1
    k_scan1     <<<NB, 256>>>();                              // launch 2
    k_scan3     <<<NB, 256>>>();                              // launch 3
    k_fill_gemm1<<<FILL_BLKS + GEMM_BLKS, 256>>>(ei, x, W1);  // launch 4
    k_agg1      <<<N_NODES / 16, 256>>>(b1, W2);              // launch 5  <- ncu -s 5
    k_agg2      <<<(N_NODES + 63) / 64, 256>>>(b2, out);      // launch 6
}